// round 5
// baseline (speedup 1.0000x reference)
#include <cuda_runtime.h>
#include <math.h>

// Problem constants (B=8, L=4096, D=1024, fp32)
#define BB 8
#define LL 4096
#define DD 1024
#define ND (LL - 1)   // 4095 deltas per batch row
#define NI (LL - 2)   // 4094 delta_increase terms per batch
#define TC 32         // loss terms per block; computes TC+1 deltas from TC+2 rows

// Accumulators. Zero-initialized at load; last block resets them each launch
// so graph replays are deterministic.
__device__ float g_ws;
__device__ float g_ms;
__device__ unsigned int g_ticket;

// Fused kernel: each block (bx, b) owns loss terms t in [32*bx, 32*bx+32) ∩ [0,NI).
// It computes deltas t0..t0+32 (rows t0..t0+33) entirely locally:
//   deltas[t]         = || states[b,t+1,:] - states[b,t,:] ||
//   delta_increase[t] = relu(deltas[t+1] - deltas[t])
//   mask[t]           = reasoning_mask[b, t+2]
//   dist              = max(rtp[b] - t - 2, 0); w = dist<5 ? 2+(5-dist)*0.5 : 1
// Block accumulates sum(di*m*w) and sum(m), one atomicAdd pair per block.
// Last block (atomic ticket) publishes out = ws/(ms+1e-9) and resets state.
//
// rtp dtype hedge: buffer may be int64 or int32. Read as 16 int32 words;
// little-endian int64 values < 4096 => all odd words zero => take even words.
__global__ __launch_bounds__(256) void fused_kernel(const float* __restrict__ states,
                                                    const float* __restrict__ reasoning_mask,
                                                    const int* __restrict__ rtp_raw,
                                                    float* __restrict__ out) {
    const int b   = blockIdx.y;
    const int t0  = blockIdx.x * TC;
    const int tid = threadIdx.x;
    const int warp = tid >> 5;
    const unsigned int nblocks = gridDim.x * gridDim.y;

    const float4* __restrict__ base =
        reinterpret_cast<const float4*>(states + (size_t)b * LL * DD);

    __shared__ float warp_sums[TC + 1][8];
    __shared__ float delta_sm[TC + 1];

    // ---- Phase 1: barrier-free delta partials (33 deltas, rows t0..t0+33) ----
    float4 prev = base[(size_t)t0 * 256 + tid];

    #pragma unroll
    for (int i = 0; i <= TC; i++) {
        const int t = t0 + i;             // delta index
        float s = 0.0f;
        float4 cur = prev;
        if (t < ND) {
            cur = base[(size_t)(t + 1) * 256 + tid];
            float dx = cur.x - prev.x;
            float dy = cur.y - prev.y;
            float dz = cur.z - prev.z;
            float dw = cur.w - prev.w;
            s = dx * dx + dy * dy + dz * dz + dw * dw;
        }
        #pragma unroll
        for (int o = 16; o > 0; o >>= 1)
            s += __shfl_xor_sync(0xffffffffu, s, o);
        if ((tid & 31) == 0) warp_sums[i][warp] = s;
        prev = cur;
    }

    __syncthreads();

    // ---- Phase 2: finish 33 deltas (threads 0..32) ----
    if (tid <= TC) {
        float v = 0.0f;
        #pragma unroll
        for (int w = 0; w < 8; w++) v += warp_sums[tid][w];
        delta_sm[tid] = sqrtf(v);
    }
    __syncthreads();

    // ---- Phase 3: loss terms, warp 0 only (32 terms, one per lane) ----
    if (warp == 0) {
        // decode rtp for this b (uniform within warp)
        int odd_or = 0;
        #pragma unroll
        for (int i = 1; i < 16; i += 2) odd_or |= rtp_raw[i];
        const int rtp_b = (odd_or == 0) ? rtp_raw[2 * b] : rtp_raw[b];

        const int t = t0 + tid;           // term index
        float ws = 0.0f, ms = 0.0f;
        if (t < NI) {
            float di = fmaxf(delta_sm[tid + 1] - delta_sm[tid], 0.0f);
            const float m = reasoning_mask[b * LL + t + 2];
            int dist = rtp_b - t - 2;
            if (dist < 0) dist = 0;
            const float w = (dist < 5) ? (2.0f + (float)(5 - dist) * 0.5f) : 1.0f;
            ws = di * m * w;
            ms = m;
        }
        #pragma unroll
        for (int o = 16; o > 0; o >>= 1) {
            ws += __shfl_xor_sync(0xffffffffu, ws, o);
            ms += __shfl_xor_sync(0xffffffffu, ms, o);
        }
        if (tid == 0) {
            atomicAdd(&g_ws, ws);
            atomicAdd(&g_ms, ms);
            __threadfence();
            const unsigned int my = atomicAdd(&g_ticket, 1u);
            if (my == nblocks - 1u) {
                __threadfence();
                const float tws = *(volatile float*)&g_ws;
                const float tms = *(volatile float*)&g_ms;
                out[0] = tws / (tms + 1e-9f);
                // reset for next graph replay (all blocks are done: safe)
                g_ws = 0.0f;
                g_ms = 0.0f;
                g_ticket = 0u;
            }
        }
    }
}

extern "C" void kernel_launch(void* const* d_in, const int* in_sizes, int n_in,
                              void* d_out, int out_size) {
    const float* states = (const float*)d_in[0];
    const float* rmask  = (const float*)d_in[1];
    const int*   rtp    = (const int*)d_in[2];
    float*       out    = (float*)d_out;

    dim3 grid((NI + TC - 1) / TC, BB);   // (128, 8) = 1024 blocks
    fused_kernel<<<grid, 256>>>(states, rmask, rtp, out);
}

// round 6
// speedup vs baseline: 1.0569x; 1.0569x over previous
#include <cuda_runtime.h>
#include <math.h>

// Problem constants (B=8, L=4096, D=1024, fp32)
#define BB 8
#define LL 4096
#define DD 1024
#define ND (LL - 1)   // 4095 deltas per batch row
#define NI (LL - 2)   // 4094 delta_increase terms per batch
#define TC 32         // loss terms per block; computes TC+1 deltas from TC+2 rows

// Accumulators. Zero-initialized at load; last block resets them each launch
// so graph replays are deterministic.
__device__ float g_ws;
__device__ float g_ms;
__device__ unsigned int g_ticket;

__device__ __forceinline__ float sqnorm_diff(float4 a, float4 b) {
    float dx = a.x - b.x, dy = a.y - b.y, dz = a.z - b.z, dw = a.w - b.w;
    return fmaf(dx, dx, fmaf(dy, dy, fmaf(dz, dz, dw * dw)));
}

// Fused kernel. Block (bx, b) owns loss terms t in [32*bx, 32*bx+32) ∩ [0,NI).
// Phase 1: pure streaming — per-lane squared-diff partials into smem, NO
//          cross-lane ops, loads issued 4 at a time (high MLP).
// Phase 2: warp-parallel reduction of the 33 x 256 partial matrix (8 LDS +
//          5 SHFL per delta), sqrt into delta_sm.
// Phase 3: warp 0 computes the 32 weighted loss terms, one atomicAdd pair
//          per block; last block (ticket) publishes out and resets state.
//
// rtp dtype hedge: buffer may be int64 or int32. Read as 16 int32 words;
// little-endian int64 values < 4096 => all odd words zero => take even words.
__global__ __launch_bounds__(256) void fused_kernel(const float* __restrict__ states,
                                                    const float* __restrict__ reasoning_mask,
                                                    const int* __restrict__ rtp_raw,
                                                    float* __restrict__ out) {
    const int b   = blockIdx.y;
    const int t0  = blockIdx.x * TC;
    const int tid = threadIdx.x;
    const int warp = tid >> 5;
    const int lane = tid & 31;
    const unsigned int nblocks = gridDim.x * gridDim.y;

    const float4* __restrict__ base =
        reinterpret_cast<const float4*>(states + (size_t)b * LL * DD);

    __shared__ float s_part[TC + 1][256];   // per-lane squared partials
    __shared__ float delta_sm[TC + 1];

    // ---- Phase 1: stream 34 rows, emit 33 per-lane partials ----
    if (t0 + TC + 1 < LL) {
        // Clean path (all rows in range). 8 chunks of 4 deltas + 1 tail delta.
        float4 prev = base[(size_t)t0 * 256 + tid];
        #pragma unroll
        for (int ch = 0; ch < 8; ch++) {
            const size_t r = (size_t)(t0 + 4 * ch + 1) * 256 + tid;
            float4 c0 = base[r];
            float4 c1 = base[r + 256];
            float4 c2 = base[r + 512];
            float4 c3 = base[r + 768];
            s_part[4 * ch + 0][tid] = sqnorm_diff(c0, prev);
            s_part[4 * ch + 1][tid] = sqnorm_diff(c1, c0);
            s_part[4 * ch + 2][tid] = sqnorm_diff(c2, c1);
            s_part[4 * ch + 3][tid] = sqnorm_diff(c3, c2);
            prev = c3;
        }
        float4 cl = base[(size_t)(t0 + TC + 1) * 256 + tid];
        s_part[TC][tid] = sqnorm_diff(cl, prev);
    } else {
        // Guarded path (last x-block only).
        float4 prev = base[(size_t)t0 * 256 + tid];
        #pragma unroll
        for (int i = 0; i <= TC; i++) {
            const int t = t0 + i;
            float s = 0.0f;
            float4 cur = prev;
            if (t < ND) {
                cur = base[(size_t)(t + 1) * 256 + tid];
                s = sqnorm_diff(cur, prev);
            }
            s_part[i][tid] = s;
            prev = cur;
        }
    }

    __syncthreads();

    // ---- Phase 2: reduce 256 partials per delta. Warp w handles deltas
    //      i = w, w+8, ..., <= TC. Lane l sums stride-32 column (conflict-free).
    for (int i = warp; i <= TC; i += 8) {
        float v = 0.0f;
        #pragma unroll
        for (int k = 0; k < 8; k++) v += s_part[i][lane + 32 * k];
        #pragma unroll
        for (int o = 16; o > 0; o >>= 1)
            v += __shfl_xor_sync(0xffffffffu, v, o);
        if (lane == 0) delta_sm[i] = sqrtf(v);
    }

    __syncthreads();

    // ---- Phase 3: loss terms, warp 0 only (32 terms, one per lane) ----
    if (warp == 0) {
        int odd_or = 0;
        #pragma unroll
        for (int i = 1; i < 16; i += 2) odd_or |= rtp_raw[i];
        const int rtp_b = (odd_or == 0) ? rtp_raw[2 * b] : rtp_raw[b];

        const int t = t0 + lane;          // term index
        float ws = 0.0f, ms = 0.0f;
        if (t < NI) {
            float di = fmaxf(delta_sm[lane + 1] - delta_sm[lane], 0.0f);
            const float m = reasoning_mask[b * LL + t + 2];
            int dist = rtp_b - t - 2;
            if (dist < 0) dist = 0;
            const float w = (dist < 5) ? (2.0f + (float)(5 - dist) * 0.5f) : 1.0f;
            ws = di * m * w;
            ms = m;
        }
        #pragma unroll
        for (int o = 16; o > 0; o >>= 1) {
            ws += __shfl_xor_sync(0xffffffffu, ws, o);
            ms += __shfl_xor_sync(0xffffffffu, ms, o);
        }
        if (lane == 0) {
            atomicAdd(&g_ws, ws);
            atomicAdd(&g_ms, ms);
            __threadfence();
            const unsigned int my = atomicAdd(&g_ticket, 1u);
            if (my == nblocks - 1u) {
                __threadfence();
                const float tws = *(volatile float*)&g_ws;
                const float tms = *(volatile float*)&g_ms;
                out[0] = tws / (tms + 1e-9f);
                // reset for next graph replay (all blocks done: safe)
                g_ws = 0.0f;
                g_ms = 0.0f;
                g_ticket = 0u;
            }
        }
    }
}

extern "C" void kernel_launch(void* const* d_in, const int* in_sizes, int n_in,
                              void* d_out, int out_size) {
    const float* states = (const float*)d_in[0];
    const float* rmask  = (const float*)d_in[1];
    const int*   rtp    = (const int*)d_in[2];
    float*       out    = (float*)d_out;

    dim3 grid((NI + TC - 1) / TC, BB);   // (128, 8) = 1024 blocks
    fused_kernel<<<grid, 256>>>(states, rmask, rtp, out);
}